// round 6
// baseline (speedup 1.0000x reference)
#include <cuda_runtime.h>
#include <math_constants.h>

#define H 1536
#define W 1536
#define HW (H*W)
#define TS 64            // output tile
#define RAD 5            // KS/2
#define TMPW 74          // TS + 2*RAD
#define DD 6             // max |offset|
#define AW 86            // TMPW + 2*DD
#define ASTR 88          // float4 row stride for A tile
#define NTH 1024
#define HSTR 68          // hsum row stride (pad vs 32 banks)
#define HS_PLANE (TMPW*HSTR)   // 5032
#define TCSTR 68         // center-tmp row stride
#define TC_PLANE (TS*TCSTR)    // 4352
#define NBX 800          // pass-1 B positions: 10 rows x 80

// smem: sA float4[AW*ASTR] | hsum[2*HS_PLANE] | tmpC[2*TC_PLANE] | sBx[NBX*3]
#define SMEM_BYTES (AW*ASTR*16 + 2*HS_PLANE*4 + 2*TC_PLANE*4 + NBX*3*4) // 205760

__device__ float g_res[HW];

__device__ __forceinline__ float sqrt_approx(float x) {
    float r;
    asm("sqrt.approx.f32 %0, %1;" : "=f"(r) : "f"(x));
    return r;
}

// horizontal shared-subtree: 5 window-11 sums from t[0..14]
__device__ __forceinline__ void hfold5(const float* t, float* s) {
    float core = __fadd_rn(__fadd_rn(__fadd_rn(t[4], t[5]), __fadd_rn(t[6], t[7])),
                           __fadd_rn(__fadd_rn(t[8], t[9]), t[10]));
    float a3 = t[3];
    float a2 = __fadd_rn(t[2], a3);
    float a1 = __fadd_rn(t[1], a2);
    float a0 = __fadd_rn(t[0], a1);
    float b11 = t[11];
    float b12 = __fadd_rn(b11, t[12]);
    float b13 = __fadd_rn(b12, t[13]);
    float b14 = __fadd_rn(b13, t[14]);
    s[0] = __fadd_rn(a0, core);
    s[1] = __fadd_rn(__fadd_rn(a1, core), b11);
    s[2] = __fadd_rn(__fadd_rn(a2, core), b12);
    s[3] = __fadd_rn(__fadd_rn(a3, core), b13);
    s[4] = __fadd_rn(core, b14);
}

__global__ __launch_bounds__(NTH, 1)
void dewarp_main(const float* __restrict__ A, const float* __restrict__ B) {
    extern __shared__ unsigned char smem_raw[];
    float4* sA  = (float4*)smem_raw;
    float*  hs0 = (float*)(smem_raw + AW*ASTR*16);
    float*  tc0 = hs0 + 2*HS_PLANE;
    float*  sBx = tc0 + 2*TC_PLANE;

    const int tid = threadIdx.x;
    const int by0 = blockIdx.y * TS, bx0 = blockIdx.x * TS;

    // ---- Load zero-padded A region as float4 (3 channels + pad) ----
    for (int i = tid; i < AW*AW; i += NTH) {
        int ay = i / AW, ax = i - ay*AW;
        int gy = by0 - (RAD+DD) + ay;
        int gx = bx0 - (RAD+DD) + ax;
        float4 v = make_float4(0.f, 0.f, 0.f, 0.f);
        if ((unsigned)gy < (unsigned)H && (unsigned)gx < (unsigned)W) {
            int g = gy*W + gx;
            v.x = A[g];
            v.y = A[g + HW];
            v.z = A[g + 2*HW];
        }
        sA[ay*ASTR + ax] = v;
    }

    // ---- sBx: B for pass-1 rows (ty 64..73), tx 0..79 ----
    for (int i = tid; i < NBX; i += NTH) {
        int row = i / 80, tx = i - row*80;
        int gy = by0 - RAD + 64 + row;
        int gx = bx0 - RAD + tx;
        float v0 = 0.f, v1 = 0.f, v2 = 0.f;
        if (tx < TMPW && (unsigned)gy < (unsigned)H && (unsigned)gx < (unsigned)W) {
            int g = gy*W + gx;
            v0 = B[g]; v1 = B[g + HW]; v2 = B[g + 2*HW];
        }
        sBx[i*3+0] = v0; sBx[i*3+1] = v1; sBx[i*3+2] = v2;
    }

    // ---- pass-0 metadata: thread = (row ty0 = tid>>4, lane owns tx0..tx0+4) ----
    const int ty0  = tid >> 4;
    const int lane = tid & 15;
    const int tx0  = lane * 5;
    float p0b0[5], p0b1[5], p0b2[5];
    unsigned vmask0 = 0;
    {
        int gy = by0 - RAD + ty0;
        #pragma unroll
        for (int j = 0; j < 5; j++) {
            int tx = tx0 + j;
            int gx = bx0 - RAD + tx;
            bool inb = (tx < TMPW) && ((unsigned)gy < (unsigned)H) && ((unsigned)gx < (unsigned)W);
            float v0 = 0.f, v1 = 0.f, v2 = 0.f;
            if (inb) {
                int g = gy*W + gx;
                v0 = B[g]; v1 = B[g + HW]; v2 = B[g + 2*HW];
            }
            p0b0[j] = v0; p0b1[j] = v1; p0b2[j] = v2;
            if (inb) vmask0 |= (1u << j);
        }
    }
    const int aidx0 = (ty0 + DD)*ASTR + (tx0 + DD);

    // ---- pass-1 metadata: tid<160 handles rows 64..73 (B from sBx) ----
    const bool act1 = (tid < 160);
    const int  ty1  = 64 + (tid >> 4);
    unsigned vmask1 = 0;
    if (act1) {
        int gy = by0 - RAD + ty1;
        #pragma unroll
        for (int j = 0; j < 5; j++) {
            int tx = tx0 + j;
            int gx = bx0 - RAD + tx;
            if ((tx < TMPW) && ((unsigned)gy < (unsigned)H) && ((unsigned)gx < (unsigned)W))
                vmask1 |= (1u << j);
        }
    }
    const int aidx1   = (ty1 + DD)*ASTR + (tx0 + DD);
    const int bx1base = ((ty1 - 64)*80 + tx0) * 3;

    // ---- phase-2 metadata: tid<512, thread = (col c2, 8-row segment) ----
    const bool act2 = (tid < 512);
    const int  c2   = tid & 63;
    const int  yo0  = ((tid >> 6) & 7) * 8;

    float wm[8], rr[8];
    #pragma unroll
    for (int j = 0; j < 8; j++) { wm[j] = CUDART_INF_F; rr[j] = 0.f; }

    __syncthreads();

    for (int o = 0; o < 169; ++o) {
        const int od  = o / 13;
        const int dxo = od - DD;           // dx outer (reference loop order)
        const int dyo = (o - od*13) - DD;  // dy inner
        const int aoff = dyo*ASTR + dxo;

        float* hs = hs0 + (o & 1)*HS_PLANE;
        float* tc = tc0 + (o & 1)*TC_PLANE;

        // ======== phase 1, pass 0: rows 0..63 ========
        {
            float v[5];
            #pragma unroll
            for (int j = 0; j < 5; j++) {
                float4 a = sA[aidx0 + aoff + j];
                float d0 = __fsub_rn(a.x, p0b0[j]);
                float d1 = __fsub_rn(a.y, p0b1[j]);
                float d2 = __fsub_rn(a.z, p0b2[j]);
                float q  = __fadd_rn(__fadd_rn(__fmul_rn(d0,d0), __fmul_rn(d1,d1)),
                                     __fmul_rn(d2,d2));
                float t  = sqrt_approx(q);
                v[j] = (vmask0 >> j & 1u) ? t : 0.f;
            }
            float t[15];
            t[0]=v[0]; t[1]=v[1]; t[2]=v[2]; t[3]=v[3]; t[4]=v[4];
            #pragma unroll
            for (int j = 0; j < 5; j++) {
                t[5+j]  = __shfl_down_sync(0xffffffffu, v[j], 1, 16);
                t[10+j] = __shfl_down_sync(0xffffffffu, v[j], 2, 16);
            }
            float s[5];
            hfold5(t, s);
            int hb = ty0*HSTR + tx0;
            #pragma unroll
            for (int j = 0; j < 5; j++)
                if (tx0 + j < 64) hs[hb + j] = s[j];
            #pragma unroll
            for (int j = 0; j < 5; j++) {
                int tx = tx0 + j;
                if (tx >= 5 && tx <= 68 && ty0 >= 5 && ty0 <= 68)
                    tc[(ty0-5)*TCSTR + (tx-5)] = v[j];
            }
        }

        // ======== phase 1, pass 1: rows 64..73 (160 threads) ========
        if (act1) {
            float v[5];
            #pragma unroll
            for (int j = 0; j < 5; j++) {
                float4 a = sA[aidx1 + aoff + j];
                float d0 = __fsub_rn(a.x, sBx[bx1base + j*3 + 0]);
                float d1 = __fsub_rn(a.y, sBx[bx1base + j*3 + 1]);
                float d2 = __fsub_rn(a.z, sBx[bx1base + j*3 + 2]);
                float q  = __fadd_rn(__fadd_rn(__fmul_rn(d0,d0), __fmul_rn(d1,d1)),
                                     __fmul_rn(d2,d2));
                float t  = sqrt_approx(q);
                v[j] = (vmask1 >> j & 1u) ? t : 0.f;
            }
            float t[15];
            t[0]=v[0]; t[1]=v[1]; t[2]=v[2]; t[3]=v[3]; t[4]=v[4];
            #pragma unroll
            for (int j = 0; j < 5; j++) {
                t[5+j]  = __shfl_down_sync(0xffffffffu, v[j], 1, 16);
                t[10+j] = __shfl_down_sync(0xffffffffu, v[j], 2, 16);
            }
            float s[5];
            hfold5(t, s);
            int hb = ty1*HSTR + tx0;
            #pragma unroll
            for (int j = 0; j < 5; j++)
                if (tx0 + j < 64) hs[hb + j] = s[j];
            #pragma unroll
            for (int j = 0; j < 5; j++) {
                int tx = tx0 + j;
                if (tx >= 5 && tx <= 68 && ty1 <= 68)
                    tc[(ty1-5)*TCSTR + (tx-5)] = v[j];
            }
        }

        __syncthreads();

        // ======== phase 2: vertical 11-tap subtree + fused argmin ========
        if (act2) {
            float u[18];
            #pragma unroll
            for (int j = 0; j < 18; j++)
                u[j] = hs[(yo0 + j)*HSTR + c2];

            float core = __fadd_rn(__fadd_rn(u[7], u[8]), __fadd_rn(u[9], u[10]));
            float a6 = u[6];
            float a5 = __fadd_rn(u[5], a6);
            float a4 = __fadd_rn(u[4], a5);
            float a3 = __fadd_rn(u[3], a4);
            float a2 = __fadd_rn(u[2], a3);
            float a1 = __fadd_rn(u[1], a2);
            float a0 = __fadd_rn(u[0], a1);
            float b11 = u[11];
            float b12 = __fadd_rn(b11, u[12]);
            float b13 = __fadd_rn(b12, u[13]);
            float b14 = __fadd_rn(b13, u[14]);
            float b15 = __fadd_rn(b14, u[15]);
            float b16 = __fadd_rn(b15, u[16]);
            float b17 = __fadd_rn(b16, u[17]);

            float s[8];
            s[0] = __fadd_rn(a0, core);
            s[1] = __fadd_rn(__fadd_rn(a1, core), b11);
            s[2] = __fadd_rn(__fadd_rn(a2, core), b12);
            s[3] = __fadd_rn(__fadd_rn(a3, core), b13);
            s[4] = __fadd_rn(__fadd_rn(a4, core), b14);
            s[5] = __fadd_rn(__fadd_rn(a5, core), b15);
            s[6] = __fadd_rn(__fadd_rn(a6, core), b16);
            s[7] = __fadd_rn(core, b17);

            #pragma unroll
            for (int j = 0; j < 8; j++) {
                float tv = tc[(yo0 + j)*TCSTR + c2];
                if (s[j] <= wm[j]) { wm[j] = s[j]; rr[j] = tv; }
            }
        }
        // no trailing sync: double buffer; next phase-1 sync orders reuse
    }

    if (act2) {
        #pragma unroll
        for (int j = 0; j < 8; j++)
            g_res[(by0 + yo0 + j)*W + bx0 + c2] = rr[j];
    }
}

// ---- final 3x3 min-pool (inf pad == clamped window) ----
__global__ void minpool3(float* __restrict__ out) {
    int x = blockIdx.x*blockDim.x + threadIdx.x;
    int y = blockIdx.y*blockDim.y + threadIdx.y;
    if (x >= W || y >= H) return;
    float m = CUDART_INF_F;
    #pragma unroll
    for (int dy = -1; dy <= 1; dy++) {
        int yy = y + dy;
        if ((unsigned)yy >= (unsigned)H) continue;
        const float* row = g_res + yy*W;
        #pragma unroll
        for (int dx = -1; dx <= 1; dx++) {
            int xx = x + dx;
            if ((unsigned)xx < (unsigned)W) m = fminf(m, row[xx]);
        }
    }
    out[y*W + x] = m;
}

extern "C" void kernel_launch(void* const* d_in, const int* in_sizes, int n_in,
                              void* d_out, int out_size) {
    const float* A = (const float*)d_in[0];
    const float* B = (const float*)d_in[1];
    float* out = (float*)d_out;

    cudaFuncSetAttribute(dewarp_main,
                         cudaFuncAttributeMaxDynamicSharedMemorySize, SMEM_BYTES);

    dim3 grid(W/TS, H/TS);
    dewarp_main<<<grid, NTH, SMEM_BYTES>>>(A, B);

    dim3 b2(32, 8);
    dim3 g2(W/32, H/8);
    minpool3<<<g2, b2>>>(out);
}

// round 7
// speedup vs baseline: 1.0487x; 1.0487x over previous
#include <cuda_runtime.h>
#include <math_constants.h>

#define H 1536
#define W 1536
#define HW (H*W)
#define TS 64            // output tile
#define RAD 5            // KS/2
#define TMPW 74          // TS + 2*RAD
#define TMPSTR 76        // padded row stride
#define DD 6             // max |offset|
#define AW 86            // TMPW + 2*DD
#define ASTR 88          // float4 row stride for A tile
#define NPOS (TMPW*TMPW) // 5476
#define NTH 1024
#define KPOS 6
#define REM (NPOS - (KPOS-1)*NTH)   // 356
#define BPLANE (TMPW*TMPSTR)        // 5624 floats
#define VSTR 76
#define SVPLANE (TS*VSTR)           // 4864 floats

// smem: sA float4[AW*ASTR] | sTmp[2*BPLANE] | sV[2*SVPLANE]
#define SMEM_BYTES (AW*ASTR*16 + 2*BPLANE*4 + 2*SVPLANE*4)  // 204992

__device__ float g_res[HW];

typedef unsigned long long ull;

__device__ __forceinline__ float sqrt_approx(float x) {
    float r;
    asm("sqrt.approx.f32 %0, %1;" : "=f"(r) : "f"(x));
    return r;
}
__device__ __forceinline__ ull pk2(float lo, float hi) {
    ull r; asm("mov.b64 %0, {%1, %2};" : "=l"(r) : "f"(lo), "f"(hi)); return r;
}
__device__ __forceinline__ void upk2(ull v, float& lo, float& hi) {
    asm("mov.b64 {%0, %1}, %2;" : "=f"(lo), "=f"(hi) : "l"(v));
}
__device__ __forceinline__ ull add2(ull a, ull b) {
    ull r; asm("add.rn.f32x2 %0, %1, %2;" : "=l"(r) : "l"(a), "l"(b)); return r;
}
__device__ __forceinline__ ull mul2(ull a, ull b) {
    ull r; asm("mul.rn.f32x2 %0, %1, %2;" : "=l"(r) : "l"(a), "l"(b)); return r;
}

__global__ __launch_bounds__(NTH, 1)
void dewarp_main(const float* __restrict__ A, const float* __restrict__ B) {
    extern __shared__ unsigned char smem_raw[];
    float4* sA    = (float4*)smem_raw;
    float*  sTmp0 = (float*)(smem_raw + AW*ASTR*16);
    float*  sV0   = sTmp0 + 2*BPLANE;

    const int tid = threadIdx.x;
    const int by0 = blockIdx.y * TS, bx0 = blockIdx.x * TS;

    // ---- Load zero-padded A region as float4 (3 channels + pad) ----
    for (int i = tid; i < AW*AW; i += NTH) {
        int ay = i / AW, ax = i - ay*AW;
        int gy = by0 - (RAD+DD) + ay;
        int gx = bx0 - (RAD+DD) + ax;
        float4 v = make_float4(0.f, 0.f, 0.f, 0.f);
        if ((unsigned)gy < (unsigned)H && (unsigned)gx < (unsigned)W) {
            int g = gy*W + gx;
            v.x = A[g];
            v.y = A[g + HW];
            v.z = A[g + 2*HW];
        }
        sA[ay*ASTR + ax] = v;
    }

    // ---- Pre-zero both tmp buffers (halo-invalid entries stay 0 forever) ----
    for (int i = tid; i < 2*BPLANE; i += NTH) sTmp0[i] = 0.f;

    // ---- B into registers (negated; packed for pairs (0,1),(2,3)) ----
    float nb0s[KPOS], nb1s[KPOS], nb2s[KPOS];
    int   abase[KPOS], tbase[KPOS];
    unsigned vldmask = 0;
    #pragma unroll
    for (int k = 0; k < KPOS; k++) {
        int pos = tid + k*NTH;
        int ty, tx;
        if (pos < NPOS) { ty = pos / TMPW; tx = pos - ty*TMPW; }
        else            { ty = 0; tx = 0; }
        int gy = by0 - RAD + ty;
        int gx = bx0 - RAD + tx;
        bool inb = (pos < NPOS) && ((unsigned)gy < (unsigned)H) && ((unsigned)gx < (unsigned)W);
        float v0 = 0.f, v1 = 0.f, v2 = 0.f;
        if (inb) {
            int g = gy*W + gx;
            v0 = B[g]; v1 = B[g + HW]; v2 = B[g + 2*HW];
        }
        nb0s[k] = -v0; nb1s[k] = -v1; nb2s[k] = -v2;
        abase[k] = (ty + DD)*ASTR + (tx + DD);
        tbase[k] = ty*TMPSTR + tx;
        if (inb) vldmask |= (1u << k);
    }
    ull nb0[2], nb1[2], nb2[2];
    #pragma unroll
    for (int kp = 0; kp < 2; kp++) {
        nb0[kp] = pk2(nb0s[kp*2], nb0s[kp*2+1]);
        nb1[kp] = pk2(nb1s[kp*2], nb1s[kp*2+1]);
        nb2[kp] = pk2(nb2s[kp*2], nb2s[kp*2+1]);
    }

    // vertical-sum ownership: 296 threads, one (column-pair, 8-row segment) each
    const bool vact = (tid < 296);
    int vcy = 0, vcp = 0;
    if (vact) { vcy = tid / 37; vcp = tid - vcy*37; }
    const int vy0 = vcy * 8;
    const int vtx = vcp * 2;

    // horizontal ownership: 4 consecutive x in one output row
    const int yo = tid >> 4;
    const int xs = (tid & 15) << 2;

    float wm0 = CUDART_INF_F, wm1 = CUDART_INF_F, wm2 = CUDART_INF_F, wm3 = CUDART_INF_F;
    float r0 = 0.f, r1 = 0.f, r2 = 0.f, r3 = 0.f;

    __syncthreads();

    for (int o = 0; o < 169; ++o) {
        const int od  = o / 13;
        const int dxo = od - DD;           // dx outer (matches reference loop order)
        const int dyo = (o - od*13) - DD;  // dy inner
        const int aoff = dyo*ASTR + dxo;

        float* sTmp = sTmp0 + (o & 1)*BPLANE;
        float* sV   = sV0   + (o & 1)*SVPLANE;

        // ---- phase 1: tmp = sqrt((d0^2 + d1^2) + d2^2), f32x2-packed pairs ----
        #pragma unroll
        for (int kp = 0; kp < 2; kp++) {
            const int k = kp*2;
            float4 aL = sA[abase[k]   + aoff];
            float4 aH = sA[abase[k+1] + aoff];
            ull ax = pk2(aL.x, aH.x);
            ull ay = pk2(aL.y, aH.y);
            ull az = pk2(aL.z, aH.z);
            ull d0 = add2(ax, nb0[kp]);   // == fsub_rn(a, b) per lane, exactly
            ull d1 = add2(ay, nb1[kp]);
            ull d2 = add2(az, nb2[kp]);
            ull q  = add2(add2(mul2(d0,d0), mul2(d1,d1)), mul2(d2,d2));
            float qlo, qhi; upk2(q, qlo, qhi);
            if (vldmask >> k     & 1u) sTmp[tbase[k]]   = sqrt_approx(qlo);
            if (vldmask >> (k+1) & 1u) sTmp[tbase[k+1]] = sqrt_approx(qhi);
        }
        // k = 4 (all threads in-range), k = 5 (tid < REM): scalar, bit-identical
        #pragma unroll
        for (int k = 4; k < 6; k++) {
            if (k < 5 || tid < REM) {
                if (vldmask >> k & 1u) {
                    float4 a = sA[abase[k] + aoff];
                    float d0 = __fadd_rn(a.x, nb0s[k]);
                    float d1 = __fadd_rn(a.y, nb1s[k]);
                    float d2 = __fadd_rn(a.z, nb2s[k]);
                    float q  = __fadd_rn(__fadd_rn(__fmul_rn(d0,d0), __fmul_rn(d1,d1)),
                                         __fmul_rn(d2,d2));
                    sTmp[tbase[k]] = sqrt_approx(q);
                }
            }
        }
        __syncthreads();

        // ---- phase 2a: vertical 11-tap subtree folds, column-pair packed ----
        if (vact) {
            const float* base = sTmp + vy0*TMPSTR + vtx;
            ull v[18];
            #pragma unroll
            for (int j = 0; j < 18; j++)
                v[j] = *(const ull*)(base + j*TMPSTR);

            ull core = add2(add2(v[7], v[8]), add2(v[9], v[10]));
            ull a6 = v[6];
            ull a5 = add2(v[5], a6);
            ull a4 = add2(v[4], a5);
            ull a3 = add2(v[3], a4);
            ull a2 = add2(v[2], a3);
            ull a1 = add2(v[1], a2);
            ull a0 = add2(v[0], a1);
            ull b11 = v[11];
            ull b12 = add2(b11, v[12]);
            ull b13 = add2(b12, v[13]);
            ull b14 = add2(b13, v[14]);
            ull b15 = add2(b14, v[15]);
            ull b16 = add2(b15, v[16]);
            ull b17 = add2(b16, v[17]);

            float* vo = sV + vy0*VSTR + vtx;
            *(ull*)(vo + 0*VSTR) = add2(a0, core);
            *(ull*)(vo + 1*VSTR) = add2(add2(a1, core), b11);
            *(ull*)(vo + 2*VSTR) = add2(add2(a2, core), b12);
            *(ull*)(vo + 3*VSTR) = add2(add2(a3, core), b13);
            *(ull*)(vo + 4*VSTR) = add2(add2(a4, core), b14);
            *(ull*)(vo + 5*VSTR) = add2(add2(a5, core), b15);
            *(ull*)(vo + 6*VSTR) = add2(add2(a6, core), b16);
            *(ull*)(vo + 7*VSTR) = add2(core, b17);
        }
        __syncthreads();

        // ---- phase 2b: horizontal 11-tap folds (shared subtree) + argmin on s ----
        {
            const float* rowp = sV + yo*VSTR + xs;
            float4 q0 = *(const float4*)rowp;
            float4 q1 = *(const float4*)(rowp + 4);
            float4 q2 = *(const float4*)(rowp + 8);
            float2 q3 = *(const float2*)(rowp + 12);
            float v0 = q0.x, v1 = q0.y, v2  = q0.z, v3  = q0.w;
            float v4 = q1.x, v5 = q1.y, v6  = q1.z, v7  = q1.w;
            float v8 = q2.x, v9 = q2.y, v10 = q2.z, v11 = q2.w;
            float v12 = q3.x, v13 = q3.y;

            float core = __fadd_rn(
                __fadd_rn(__fadd_rn(v3, v4), __fadd_rn(v5, v6)),
                __fadd_rn(__fadd_rn(v7, v8), __fadd_rn(v9, v10)));
            float a2 = v2;
            float a1 = __fadd_rn(v1, a2);
            float a0 = __fadd_rn(v0, a1);
            float c11 = v11;
            float c12 = __fadd_rn(c11, v12);
            float c13 = __fadd_rn(c12, v13);

            float s0 = __fadd_rn(a0, core);
            float s1 = __fadd_rn(__fadd_rn(a1, core), c11);
            float s2 = __fadd_rn(__fadd_rn(a2, core), c12);
            float s3 = __fadd_rn(core, c13);

            const int cb = (yo + RAD)*TMPSTR + (xs + RAD);
            float t0 = sTmp[cb + 0];
            float t1 = sTmp[cb + 1];
            float t2 = sTmp[cb + 2];
            float t3 = sTmp[cb + 3];

            // argmin over s (== argmin over w = s/121); ties -> newer candidate
            if (s0 <= wm0) { wm0 = s0; r0 = t0; }
            if (s1 <= wm1) { wm1 = s1; r1 = t1; }
            if (s2 <= wm2) { wm2 = s2; r2 = t2; }
            if (s3 <= wm3) { wm3 = s3; r3 = t3; }
        }
        // no trailing sync: double buffer; the sync after next phase-1 orders reuse
    }

    float4 out4 = make_float4(r0, r1, r2, r3);
    *(float4*)(g_res + (by0 + yo)*W + (bx0 + xs)) = out4;
}

// ---- final 3x3 min-pool (inf pad == clamped window) ----
__global__ void minpool3(float* __restrict__ out) {
    int x = blockIdx.x*blockDim.x + threadIdx.x;
    int y = blockIdx.y*blockDim.y + threadIdx.y;
    if (x >= W || y >= H) return;
    float m = CUDART_INF_F;
    #pragma unroll
    for (int dy = -1; dy <= 1; dy++) {
        int yy = y + dy;
        if ((unsigned)yy >= (unsigned)H) continue;
        const float* row = g_res + yy*W;
        #pragma unroll
        for (int dx = -1; dx <= 1; dx++) {
            int xx = x + dx;
            if ((unsigned)xx < (unsigned)W) m = fminf(m, row[xx]);
        }
    }
    out[y*W + x] = m;
}

extern "C" void kernel_launch(void* const* d_in, const int* in_sizes, int n_in,
                              void* d_out, int out_size) {
    const float* A = (const float*)d_in[0];
    const float* B = (const float*)d_in[1];
    float* out = (float*)d_out;

    cudaFuncSetAttribute(dewarp_main,
                         cudaFuncAttributeMaxDynamicSharedMemorySize, SMEM_BYTES);

    dim3 grid(W/TS, H/TS);
    dewarp_main<<<grid, NTH, SMEM_BYTES>>>(A, B);

    dim3 b2(32, 8);
    dim3 g2(W/32, H/8);
    minpool3<<<g2, b2>>>(out);
}

// round 8
// speedup vs baseline: 1.0725x; 1.0227x over previous
#include <cuda_runtime.h>
#include <math_constants.h>

#define H 1536
#define W 1536
#define HW (H*W)
#define TS 64            // output tile
#define RAD 5            // KS/2
#define TMPW 74          // TS + 2*RAD
#define TMPSTR 76        // padded row stride
#define DD 6             // max |offset|
#define AW 86            // TMPW + 2*DD
#define ASTR 88          // A plane row stride (floats)
#define APLANE (AW*ASTR) // 7568
#define NPOS (TMPW*TMPW) // 5476
#define NTH 1024
#define KPOS 6
#define REM (NPOS - (KPOS-1)*NTH)   // 356
#define BPLANE (TMPW*TMPSTR)        // 5624 floats
#define VSTR 76
#define SVPLANE (TS*VSTR)           // 4864 floats

// smem: sA planes[3*APLANE] | sTmp[2*BPLANE] | sV[2*SVPLANE]
#define SMEM_BYTES (3*APLANE*4 + 2*BPLANE*4 + 2*SVPLANE*4)  // 174720

__device__ float g_res[HW];

typedef unsigned long long ull;

__device__ __forceinline__ float sqrt_approx(float x) {
    float r;
    asm("sqrt.approx.f32 %0, %1;" : "=f"(r) : "f"(x));
    return r;
}
__device__ __forceinline__ ull pk2(float lo, float hi) {
    ull r; asm("mov.b64 %0, {%1, %2};" : "=l"(r) : "f"(lo), "f"(hi)); return r;
}
__device__ __forceinline__ void upk2(ull v, float& lo, float& hi) {
    asm("mov.b64 {%0, %1}, %2;" : "=f"(lo), "=f"(hi) : "l"(v));
}
__device__ __forceinline__ ull add2(ull a, ull b) {
    ull r; asm("add.rn.f32x2 %0, %1, %2;" : "=l"(r) : "l"(a), "l"(b)); return r;
}
__device__ __forceinline__ ull mul2(ull a, ull b) {
    ull r; asm("mul.rn.f32x2 %0, %1, %2;" : "=l"(r) : "l"(a), "l"(b)); return r;
}

__global__ __launch_bounds__(NTH, 1)
void dewarp_main(const float* __restrict__ A, const float* __restrict__ B) {
    extern __shared__ unsigned char smem_raw[];
    float* sA0   = (float*)smem_raw;
    float* sA1   = sA0 + APLANE;
    float* sA2   = sA1 + APLANE;
    float* sTmpB = sA2 + APLANE;          // 2 buffers
    float* sVB   = sTmpB + 2*BPLANE;      // 2 buffers

    const int tid = threadIdx.x;
    const int by0 = blockIdx.y * TS, bx0 = blockIdx.x * TS;

    // ---- Load zero-padded A region into 3 planes ----
    for (int i = tid; i < AW*AW; i += NTH) {
        int ay = i / AW, ax = i - ay*AW;
        int gy = by0 - (RAD+DD) + ay;
        int gx = bx0 - (RAD+DD) + ax;
        float v0 = 0.f, v1 = 0.f, v2 = 0.f;
        if ((unsigned)gy < (unsigned)H && (unsigned)gx < (unsigned)W) {
            int g = gy*W + gx;
            v0 = A[g]; v1 = A[g + HW]; v2 = A[g + 2*HW];
        }
        int s = ay*ASTR + ax;
        sA0[s] = v0; sA1[s] = v1; sA2[s] = v2;
    }

    // ---- Pre-zero both tmp buffers (halo-invalid entries stay 0 forever) ----
    for (int i = tid; i < 2*BPLANE; i += NTH) sTmpB[i] = 0.f;

    // ---- B into registers (negated; packed for pairs (0,1),(2,3)) ----
    float nb0s[KPOS], nb1s[KPOS], nb2s[KPOS];
    int   abase[KPOS], tbase[KPOS];
    unsigned vldmask = 0;
    #pragma unroll
    for (int k = 0; k < KPOS; k++) {
        int pos = tid + k*NTH;
        int ty, tx;
        if (pos < NPOS) { ty = pos / TMPW; tx = pos - ty*TMPW; }
        else            { ty = 0; tx = 0; }
        int gy = by0 - RAD + ty;
        int gx = bx0 - RAD + tx;
        bool inb = (pos < NPOS) && ((unsigned)gy < (unsigned)H) && ((unsigned)gx < (unsigned)W);
        float v0 = 0.f, v1 = 0.f, v2 = 0.f;
        if (inb) {
            int g = gy*W + gx;
            v0 = B[g]; v1 = B[g + HW]; v2 = B[g + 2*HW];
        }
        nb0s[k] = -v0; nb1s[k] = -v1; nb2s[k] = -v2;
        abase[k] = (ty + DD)*ASTR + (tx + DD);
        tbase[k] = ty*TMPSTR + tx;
        if (inb) vldmask |= (1u << k);
    }
    ull nb0[2], nb1[2], nb2[2];
    #pragma unroll
    for (int kp = 0; kp < 2; kp++) {
        nb0[kp] = pk2(nb0s[kp*2], nb0s[kp*2+1]);
        nb1[kp] = pk2(nb1s[kp*2], nb1s[kp*2+1]);
        nb2[kp] = pk2(nb2s[kp*2], nb2s[kp*2+1]);
    }

    // phase-2a ownership: 592 threads = 2 offsets x 37 column-pairs x 8-row segs
    const bool vact = (tid < 592);
    const int  voff = (tid >= 296) ? 1 : 0;
    const int  vt   = tid - 296*voff;
    const int  vy0  = (vt / 37) * 8;
    const int  vtx  = (vt % 37) * 2;

    // phase-2b ownership: 4 consecutive x in one output row
    const int yo = tid >> 4;
    const int xs = (tid & 15) << 2;

    float wm0 = CUDART_INF_F, wm1 = CUDART_INF_F, wm2 = CUDART_INF_F, wm3 = CUDART_INF_F;
    float r0 = 0.f, r1 = 0.f, r2 = 0.f, r3 = 0.f;

    __syncthreads();

    for (int op = 0; op < 85; ++op) {
        const int o0 = 2*op;
        const bool has1 = (o0 + 1) < 169;

        // ======== phase 1: tmp for o0 (buffer 0) and o1 (buffer 1) ========
        #pragma unroll
        for (int half = 0; half < 2; half++) {
            const int o = o0 + half;
            if (half == 1 && !has1) break;
            const int od  = o / 13;
            const int dxo = od - DD;           // dx outer (reference loop order)
            const int dyo = (o - od*13) - DD;  // dy inner
            const int aoff = dyo*ASTR + dxo;
            float* sTmp = sTmpB + half*BPLANE;

            #pragma unroll
            for (int kp = 0; kp < 2; kp++) {
                const int k = kp*2;
                int iaL = abase[k]   + aoff;
                int iaH = abase[k+1] + aoff;
                ull ax = pk2(sA0[iaL], sA0[iaH]);
                ull ay = pk2(sA1[iaL], sA1[iaH]);
                ull az = pk2(sA2[iaL], sA2[iaH]);
                ull d0 = add2(ax, nb0[kp]);   // == fsub_rn per lane, exactly
                ull d1 = add2(ay, nb1[kp]);
                ull d2 = add2(az, nb2[kp]);
                ull q  = add2(add2(mul2(d0,d0), mul2(d1,d1)), mul2(d2,d2));
                float qlo, qhi; upk2(q, qlo, qhi);
                if (vldmask >> k     & 1u) sTmp[tbase[k]]   = sqrt_approx(qlo);
                if (vldmask >> (k+1) & 1u) sTmp[tbase[k+1]] = sqrt_approx(qhi);
            }
            #pragma unroll
            for (int k = 4; k < 6; k++) {
                if (k < 5 || tid < REM) {
                    if (vldmask >> k & 1u) {
                        int ia = abase[k] + aoff;
                        float d0 = __fadd_rn(sA0[ia], nb0s[k]);
                        float d1 = __fadd_rn(sA1[ia], nb1s[k]);
                        float d2 = __fadd_rn(sA2[ia], nb2s[k]);
                        float q  = __fadd_rn(__fadd_rn(__fmul_rn(d0,d0), __fmul_rn(d1,d1)),
                                             __fmul_rn(d2,d2));
                        sTmp[tbase[k]] = sqrt_approx(q);
                    }
                }
            }
        }
        __syncthreads();

        // ======== phase 2a: vertical 11-tap subtree folds, both offsets ========
        if (vact && (voff == 0 || has1)) {
            const float* sTmp = sTmpB + voff*BPLANE;
            float*       sV   = sVB   + voff*SVPLANE;
            const float* base = sTmp + vy0*TMPSTR + vtx;
            ull v[18];
            #pragma unroll
            for (int j = 0; j < 18; j++)
                v[j] = *(const ull*)(base + j*TMPSTR);

            ull core = add2(add2(v[7], v[8]), add2(v[9], v[10]));
            ull a6 = v[6];
            ull a5 = add2(v[5], a6);
            ull a4 = add2(v[4], a5);
            ull a3 = add2(v[3], a4);
            ull a2 = add2(v[2], a3);
            ull a1 = add2(v[1], a2);
            ull a0 = add2(v[0], a1);
            ull b11 = v[11];
            ull b12 = add2(b11, v[12]);
            ull b13 = add2(b12, v[13]);
            ull b14 = add2(b13, v[14]);
            ull b15 = add2(b14, v[15]);
            ull b16 = add2(b15, v[16]);
            ull b17 = add2(b16, v[17]);

            float* vo = sV + vy0*VSTR + vtx;
            *(ull*)(vo + 0*VSTR) = add2(a0, core);
            *(ull*)(vo + 1*VSTR) = add2(add2(a1, core), b11);
            *(ull*)(vo + 2*VSTR) = add2(add2(a2, core), b12);
            *(ull*)(vo + 3*VSTR) = add2(add2(a3, core), b13);
            *(ull*)(vo + 4*VSTR) = add2(add2(a4, core), b14);
            *(ull*)(vo + 5*VSTR) = add2(add2(a5, core), b15);
            *(ull*)(vo + 6*VSTR) = add2(add2(a6, core), b16);
            *(ull*)(vo + 7*VSTR) = add2(core, b17);
        }
        __syncthreads();

        // ======== phase 2b: horizontal folds + argmin, o0 then o1 ========
        #pragma unroll
        for (int half = 0; half < 2; half++) {
            if (half == 1 && !has1) break;
            const float* sTmp = sTmpB + half*BPLANE;
            const float* sV   = sVB   + half*SVPLANE;

            const float* rowp = sV + yo*VSTR + xs;
            float4 q0 = *(const float4*)rowp;
            float4 q1 = *(const float4*)(rowp + 4);
            float4 q2 = *(const float4*)(rowp + 8);
            float2 q3 = *(const float2*)(rowp + 12);
            float v0 = q0.x, v1 = q0.y, v2  = q0.z, v3  = q0.w;
            float v4 = q1.x, v5 = q1.y, v6  = q1.z, v7  = q1.w;
            float v8 = q2.x, v9 = q2.y, v10 = q2.z, v11 = q2.w;
            float v12 = q3.x, v13 = q3.y;

            float core = __fadd_rn(
                __fadd_rn(__fadd_rn(v3, v4), __fadd_rn(v5, v6)),
                __fadd_rn(__fadd_rn(v7, v8), __fadd_rn(v9, v10)));
            float a2 = v2;
            float a1 = __fadd_rn(v1, a2);
            float a0 = __fadd_rn(v0, a1);
            float c11 = v11;
            float c12 = __fadd_rn(c11, v12);
            float c13 = __fadd_rn(c12, v13);

            float s0 = __fadd_rn(a0, core);
            float s1 = __fadd_rn(__fadd_rn(a1, core), c11);
            float s2 = __fadd_rn(__fadd_rn(a2, core), c12);
            float s3 = __fadd_rn(core, c13);

            const int cb = (yo + RAD)*TMPSTR + (xs + RAD);
            float t0 = sTmp[cb + 0];
            float t1 = sTmp[cb + 1];
            float t2 = sTmp[cb + 2];
            float t3 = sTmp[cb + 3];

            // argmin over s (== argmin over w = s/121); ties -> newer candidate
            if (s0 <= wm0) { wm0 = s0; r0 = t0; }
            if (s1 <= wm1) { wm1 = s1; r1 = t1; }
            if (s2 <= wm2) { wm2 = s2; r2 = t2; }
            if (s3 <= wm3) { wm3 = s3; r3 = t3; }
        }
        __syncthreads();   // protect sTmp/sV before next pair's phase 1
    }

    float4 out4 = make_float4(r0, r1, r2, r3);
    *(float4*)(g_res + (by0 + yo)*W + (bx0 + xs)) = out4;
}

// ---- final 3x3 min-pool (inf pad == clamped window) ----
__global__ void minpool3(float* __restrict__ out) {
    int x = blockIdx.x*blockDim.x + threadIdx.x;
    int y = blockIdx.y*blockDim.y + threadIdx.y;
    if (x >= W || y >= H) return;
    float m = CUDART_INF_F;
    #pragma unroll
    for (int dy = -1; dy <= 1; dy++) {
        int yy = y + dy;
        if ((unsigned)yy >= (unsigned)H) continue;
        const float* row = g_res + yy*W;
        #pragma unroll
        for (int dx = -1; dx <= 1; dx++) {
            int xx = x + dx;
            if ((unsigned)xx < (unsigned)W) m = fminf(m, row[xx]);
        }
    }
    out[y*W + x] = m;
}

extern "C" void kernel_launch(void* const* d_in, const int* in_sizes, int n_in,
                              void* d_out, int out_size) {
    const float* A = (const float*)d_in[0];
    const float* B = (const float*)d_in[1];
    float* out = (float*)d_out;

    cudaFuncSetAttribute(dewarp_main,
                         cudaFuncAttributeMaxDynamicSharedMemorySize, SMEM_BYTES);

    dim3 grid(W/TS, H/TS);
    dewarp_main<<<grid, NTH, SMEM_BYTES>>>(A, B);

    dim3 b2(32, 8);
    dim3 g2(W/32, H/8);
    minpool3<<<g2, b2>>>(out);
}